// round 16
// baseline (speedup 1.0000x reference)
#include <cuda_runtime.h>

// StDevLoss: 7x7 clamped-window 3D-point-distance std, summed, x100.
// depthin (1,1,480,640) fp32 -> scalar fp32. Single fused kernel.
// Round 16: window split across 2 threads (column halves j=0..2 / j=3..6)
// to double resident warps; row-paired pixels; (z,z^2) smem; 42-reg cap.

#define ROWS 480
#define COLS 640

#define CXB 16                // pixel columns per block
#define RPB 4                 // row-pairs per block (8 pixel rows)
#define NT  128               // (16, 4, 2)
#define TW (CXB + 6)          // 22
#define TH (2 * RPB + 6)      // 14
#define TP 24                 // shared row stride (float2 units)

#define GRIDX (COLS / CXB)        // 40
#define GRIDY (ROWS / (2 * RPB))  // 60
#define NPART (GRIDX * GRIDY)     // 2400

#define CXc   313.0447587080473f
#define CYc   238.44389626620386f
#define INVFX (1.0f / 582.6244816773795f)
#define INVFY (1.0f / 582.6910327098864f)

__device__ float g_partials[NPART];
__device__ unsigned int g_count = 0;

// sqrt(|x|): abs folds into the MUFU operand modifier; sqrt.approx(0)==0.
__device__ __forceinline__ float sqrt_abs(float x) {
    float r;
    asm("{\n\t.reg .f32 t;\n\tabs.f32 t, %1;\n\tsqrt.approx.f32 %0, t;\n\t}"
        : "=f"(r) : "f"(x));
    return r;
}

struct Ctr { float m2x, m2y, m2z, pc2; };

// One window row, NJ columns, up to two pixels (P0/P1 compile-time).
template<int NJ, bool P0, bool P1>
__device__ __forceinline__ void do_row(const float2* __restrict__ rowp,
                                       const float* __restrict__ cf, float rf,
                                       const Ctr& A, const Ctr& B,
                                       float& s1_0, float& s2_0,
                                       float& s1_1, float& s2_1) {
    const float r2p1 = fmaf(rf, rf, 1.0f);
    const float a0 = P0 ? fmaf(A.m2y, rf, A.m2z) : 0.0f;
    const float a1 = P1 ? fmaf(B.m2y, rf, B.m2z) : 0.0f;
    #pragma unroll
    for (int j = 0; j < NJ; j++) {
        const float2 zz = rowp[j];                   // (zn, zn^2): one LDS.64
        const float qg = fmaf(cf[j], cf[j], r2p1);   // cf^2 + rf^2 + 1 (shared)
        if (P0) {
            const float q  = fmaf(zz.y, qg, A.pc2);
            const float m  = fmaf(A.m2x, cf[j], a0);
            const float ss = fmaf(zz.x, m, q);
            s1_0 += sqrt_abs(ss);
            s2_0 += ss;
        }
        if (P1) {
            const float q  = fmaf(zz.y, qg, B.pc2);
            const float m  = fmaf(B.m2x, cf[j], a1);
            const float ss = fmaf(zz.x, m, q);
            s1_1 += sqrt_abs(ss);
            s2_1 += ss;
        }
    }
}

template<int NJ>
__device__ __forceinline__ void process_windows(const float2* __restrict__ rp0,
                                                const float* __restrict__ cf,
                                                float rf0, int d10,
                                                const Ctr& A, const Ctr& B,
                                                float& s1_0, float& s2_0,
                                                float& s1_1, float& s2_1) {
    if (d10 == 0) {
        #pragma unroll
        for (int t = 0; t < 7; t++)
            do_row<NJ, true, true>(rp0 + t * TP, cf, rf0 + (float)t * INVFY,
                                   A, B, s1_0, s2_0, s1_1, s2_1);
    } else {
        do_row<NJ, true, false>(rp0, cf, rf0, A, B, s1_0, s2_0, s1_1, s2_1);
        #pragma unroll
        for (int t = 1; t <= 6; t++)
            do_row<NJ, true, true>(rp0 + t * TP, cf, rf0 + (float)t * INVFY,
                                   A, B, s1_0, s2_0, s1_1, s2_1);
        do_row<NJ, false, true>(rp0 + 7 * TP, cf, rf0 + 7.0f * INVFY,
                                A, B, s1_0, s2_0, s1_1, s2_1);
    }
}

__global__ __launch_bounds__(NT, 12)
void stdev_kernel(const float* __restrict__ depth, float* __restrict__ out) {
    __shared__ float2 shz[TH * TP];        // (z, z^2)
    __shared__ float comb[4][CXB * RPB];   // half-combine: s1_0,s2_0,s1_1,s2_1
    __shared__ float red[NT / 32];
    __shared__ unsigned int s_last;

    const int cx  = threadIdx.x;           // 0..15 pixel column
    const int rp  = threadIdx.y;           // 0..3  row-pair
    const int h   = threadIdx.z;           // 0..1  column half (warp-uniform)
    const int tid = cx + CXB * rp + 64 * h;
    const int c0  = blockIdx.x * CXB;
    const int r0  = blockIdx.y * (2 * RPB);

    // Structured haloed (z, z^2) tile load: rows {g, g+4, g+8, g+12}, g=tid>>5.
    {
        const int sc  = tid & 31;
        const int sr0 = tid >> 5;
        if (sc < TW) {
            #pragma unroll
            for (int srb = 0; srb < 16; srb += 4) {
                const int sr = sr0 + srb;
                if (sr < TH) {
                    const int gr = min(max(r0 - 3 + sr, 0), ROWS - 1);
                    const int gc = min(max(c0 - 3 + sc, 0), COLS - 1);
                    const float d = depth[gr * COLS + gc];
                    const float z = (d > 0.0f && d < 1.01f) ? d * 1e-3f : 0.0f;
                    shz[sr * TP + sc] = make_float2(z, z * z);
                }
            }
        }
    }
    __syncthreads();

    const int c    = c0 + cx;
    const int jb   = min(max(c - 3, 0), COLS - 7);
    const int jb_s = jb - c0 + 3;
    const int j0   = (h == 0) ? 0 : 3;     // column-half start

    float cf[4];
    #pragma unroll
    for (int jj = 0; jj < 4; jj++)
        cf[jj] = ((float)(jb + j0 + jj) - CXc) * INVFX;

    // Two consecutive pixel rows per thread-pair (warp-uniform rp).
    const int ra  = r0 + 2 * rp;
    const int rb  = ra + 1;
    const int ib0 = min(max(ra - 3, 0), ROWS - 7);
    const int ib1 = min(max(rb - 3, 0), ROWS - 7);
    const int d10 = ib1 - ib0;             // 0 or 1
    const int base_s = ib0 - r0 + 3;

    const float cfc = ((float)c - CXc) * INVFX;
    const float zc0 = shz[(2 * rp + 3) * TP + (cx + 3)].x;
    const float zc1 = shz[(2 * rp + 4) * TP + (cx + 3)].x;

    Ctr A, B;
    {
        const float xc = zc0 * cfc, yc = zc0 * (((float)ra - CYc) * INVFY);
        float p = xc * xc; p = fmaf(yc, yc, p); p = fmaf(zc0, zc0, p);
        A.m2x = -2.0f * xc; A.m2y = -2.0f * yc; A.m2z = -2.0f * zc0; A.pc2 = p;
    }
    {
        const float xc = zc1 * cfc, yc = zc1 * (((float)rb - CYc) * INVFY);
        float p = xc * xc; p = fmaf(yc, yc, p); p = fmaf(zc1, zc1, p);
        B.m2x = -2.0f * xc; B.m2y = -2.0f * yc; B.m2z = -2.0f * zc1; B.pc2 = p;
    }

    float s1_0 = 0.0f, s2_0 = 0.0f, s1_1 = 0.0f, s2_1 = 0.0f;
    const float2* __restrict__ rp0 = &shz[base_s * TP + jb_s + j0];
    const float rf0 = ((float)ib0 - CYc) * INVFY;

    if (h == 0)
        process_windows<3>(rp0, cf, rf0, d10, A, B, s1_0, s2_0, s1_1, s2_1);
    else
        process_windows<4>(rp0, cf, rf0, d10, A, B, s1_0, s2_0, s1_1, s2_1);

    // Combine column halves: h=1 publishes, h=0 finishes both pixels.
    const int key = rp * CXB + cx;
    if (h == 1) {
        comb[0][key] = s1_0; comb[1][key] = s2_0;
        comb[2][key] = s1_1; comb[3][key] = s2_1;
    }
    __syncthreads();

    float total = 0.0f;
    if (h == 0) {
        const float s1p0 = s1_0 + comb[0][key];
        const float s2p0 = s2_0 + comb[1][key];
        const float s1p1 = s1_1 + comb[2][key];
        const float s2p1 = s2_1 + comb[3][key];

        // var = (sum d^2 - (sum d)^2/49) / 48  (Bessel-corrected)
        const float mean0 = s1p0 * (1.0f / 49.0f);
        float var0 = fmaf(-mean0, s1p0, s2p0) * (1.0f / 48.0f);
        var0 = fmaxf(var0, 0.0f);
        const float mean1 = s1p1 * (1.0f / 49.0f);
        float var1 = fmaf(-mean1, s1p1, s2p1) * (1.0f / 48.0f);
        var1 = fmaxf(var1, 0.0f);
        total  = (zc0 > 0.0f) ? sqrt_abs(var0) : 0.0f;
        total += (zc1 > 0.0f) ? sqrt_abs(var1) : 0.0f;
    }

    // Deterministic warp shuffle reduction, then cross-warp via smem.
    #pragma unroll
    for (int k = 16; k > 0; k >>= 1)
        total += __shfl_down_sync(0xFFFFFFFFu, total, k);
    if ((tid & 31) == 0) red[tid >> 5] = total;
    __syncthreads();

    // Fused final reduction: last arriving block sums all partials in
    // fixed index order (deterministic), writes out, re-arms counter.
    if (tid == 0) {
        g_partials[blockIdx.y * GRIDX + blockIdx.x] =
            (red[0] + red[1]) + (red[2] + red[3]);
        __threadfence();
        const unsigned int t = atomicAdd(&g_count, 1u);
        s_last = (t == NPART - 1) ? 1u : 0u;
    }
    __syncthreads();

    if (s_last) {
        const volatile float* vp = g_partials;
        float s = 0.0f;
        for (int i = tid; i < NPART; i += NT) s += vp[i];
        #pragma unroll
        for (int k = 16; k > 0; k >>= 1)
            s += __shfl_down_sync(0xFFFFFFFFu, s, k);
        if ((tid & 31) == 0) red[tid >> 5] = s;
        __syncthreads();
        if (tid == 0) {
            out[0] = ((red[0] + red[1]) + (red[2] + red[3])) * 100.0f;
            g_count = 0;   // re-arm for next graph replay
        }
    }
}

extern "C" void kernel_launch(void* const* d_in, const int* in_sizes, int n_in,
                              void* d_out, int out_size) {
    const float* depth = (const float*)d_in[0];
    float* out = (float*)d_out;

    dim3 grid(GRIDX, GRIDY);
    dim3 block(CXB, RPB, 2);
    stdev_kernel<<<grid, block>>>(depth, out);
}

// round 17
// speedup vs baseline: 1.2737x; 1.2737x over previous
#include <cuda_runtime.h>

// StDevLoss: 7x7 clamped-window 3D-point-distance std, summed, x100.
// depthin (1,1,480,640) fp32 -> scalar fp32. Single fused kernel.
// Round 17: R15 base (row-paired pixels as f32x2 lanes, minimal-issue
// inner loop) + front-batched row loads (MLP=7 on the smem port) + 64-reg
// budget so the batch lives in registers.

#define ROWS 480
#define COLS 640

#define BX 32
#define BY 4
#define NT (BX * BY)          // 128 threads; thread owns rows r0+2ty, +1
#define PIX_Y 8
#define TW (BX + 6)           // 38
#define TH (PIX_Y + 6)        // 14
#define TP 40                 // shared row stride (float2 units)

#define GRIDX (COLS / BX)     // 20
#define GRIDY (ROWS / PIX_Y)  // 60
#define NPART (GRIDX * GRIDY) // 1200

__device__ float g_partials[NPART];
__device__ unsigned int g_count = 0;

typedef unsigned long long u64;

// sqrt(|x|): abs folds into the MUFU operand modifier; sqrt.approx(0)==0.
__device__ __forceinline__ float sqrt_abs(float x) {
    float r;
    asm("{\n\t.reg .f32 t;\n\tabs.f32 t, %1;\n\tsqrt.approx.f32 %0, t;\n\t}"
        : "=f"(r) : "f"(x));
    return r;
}
__device__ __forceinline__ u64 pack2(float lo, float hi) {
    u64 r;
    asm("mov.b64 %0, {%1, %2};" : "=l"(r) : "f"(lo), "f"(hi));
    return r;
}
__device__ __forceinline__ void unpack2(u64 v, float& lo, float& hi) {
    asm("mov.b64 {%0, %1}, %2;" : "=f"(lo), "=f"(hi) : "l"(v));
}
__device__ __forceinline__ u64 add2(u64 a, u64 b) {
    u64 r;
    asm("add.rn.f32x2 %0, %1, %2;" : "=l"(r) : "l"(a), "l"(b));
    return r;
}
__device__ __forceinline__ u64 fma2(u64 a, u64 b, u64 c) {
    u64 r;
    asm("fma.rn.f32x2 %0, %1, %2, %3;" : "=l"(r) : "l"(a), "l"(b), "l"(c));
    return r;
}

// Packed row, loads front-batched: 7 LDS.64 issue back-to-back (MLP=7),
// then the compute loop runs load-free.
__device__ __forceinline__ void row2(const u64* __restrict__ rowp,
                                     const u64* __restrict__ cfd, float rf,
                                     float m2y0, float m2z0,
                                     float m2y1, float m2z1,
                                     u64 m2x01, u64 pc201,
                                     float& s1_0, float& s1_1, u64& s2p) {
    u64 z[7];
    #pragma unroll
    for (int j = 0; j < 7; j++) z[j] = rowp[j];      // batched LDS.64

    const float r2p1 = fmaf(rf, rf, 1.0f);
    const u64 r2p101 = pack2(r2p1, r2p1);
    const u64 a01 = pack2(fmaf(m2y0, rf, m2z0), fmaf(m2y1, rf, m2z1));
    #pragma unroll
    for (int j = 0; j < 7; j++) {
        const u64 qg = fma2(cfd[j], cfd[j], r2p101); // cf^2 + rf^2 + 1
        const u64 m  = fma2(m2x01, cfd[j], a01);     // m2x*cf + a
        const u64 t  = fma2(z[j], qg, m);            // zn*qg + m
        const u64 ss = fma2(z[j], t, pc201);         // zn*t + pc2
        float ss0, ss1;
        unpack2(ss, ss0, ss1);                       // register halves
        s1_0 += sqrt_abs(ss0);
        s1_1 += sqrt_abs(ss1);
        s2p = add2(s2p, ss);
    }
}

// Scalar row: one pixel active (clamped-edge rows; runs at most once/thread).
__device__ __forceinline__ void row1(const u64* __restrict__ rowp,
                                     const u64* __restrict__ cfd, float rf,
                                     float m2y, float m2z, float m2x,
                                     float pc2, float& s1, float& s2e) {
    const float r2p1 = fmaf(rf, rf, 1.0f);
    const float a = fmaf(m2y, rf, m2z);
    #pragma unroll
    for (int j = 0; j < 7; j++) {
        float cf, cfh, zn, znh;
        unpack2(cfd[j], cf, cfh);
        unpack2(rowp[j], zn, znh);
        (void)cfh; (void)znh;
        const float qg = fmaf(cf, cf, r2p1);
        const float m  = fmaf(m2x, cf, a);
        const float t  = fmaf(zn, qg, m);
        const float ss = fmaf(zn, t, pc2);
        s1 += sqrt_abs(ss);
        s2e += ss;
    }
}

__global__ __launch_bounds__(NT, 8)
void stdev_kernel(const float* __restrict__ depth, float* __restrict__ out) {
    const float CXc   = 313.0447587080473f;
    const float CYc   = 238.44389626620386f;
    const float invFX = 1.0f / 582.6244816773795f;
    const float invFY = 1.0f / 582.6910327098864f;

    __shared__ float2 shz[TH * TP];      // (z, z) duplicated
    __shared__ float red[NT / 32];
    __shared__ unsigned int s_last;

    const int tx  = threadIdx.x;
    const int ty  = threadIdx.y;
    const int tid = ty * BX + tx;
    const int c0  = blockIdx.x * BX;
    const int r0  = blockIdx.y * PIX_Y;

    // Div-free cooperative haloed (z, z) tile load. Clamped halo cells are
    // never read by the clamped-window logic but must be finite.
    #pragma unroll
    for (int sr = 0; sr < TH; sr += BY) {
        const int srr = sr + ty;
        if (srr < TH) {
            const int gr = min(max(r0 - 3 + srr, 0), ROWS - 1);
            const float* __restrict__ drow = depth + gr * COLS;
            #pragma unroll
            for (int sc0 = 0; sc0 < TW; sc0 += BX) {
                const int sc = sc0 + tx;
                if (sc < TW) {
                    const int gc = min(max(c0 - 3 + sc, 0), COLS - 1);
                    const float d = drow[gc];
                    const float z = (d > 0.0f && d < 1.01f) ? d * 1e-3f : 0.0f;
                    shz[srr * TP + sc] = make_float2(z, z);
                }
            }
        }
    }
    __syncthreads();

    const int c    = c0 + tx;
    const int jb   = min(max(c - 3, 0), COLS - 7);
    const int jb_s = jb - c0 + 3;
    const float cfc = ((float)c - CXc) * invFX;

    // Packed per-column factors (cf_j, cf_j).
    u64 cfd[7];
    {
        float v = ((float)jb - CXc) * invFX;
        #pragma unroll
        for (int j = 0; j < 7; j++) { cfd[j] = pack2(v, v); v += invFX; }
    }

    // Two consecutive pixel rows per thread (warp-uniform: warp == one ty).
    const int ra  = r0 + 2 * ty;
    const int rb  = ra + 1;
    const int ib0 = min(max(ra - 3, 0), ROWS - 7);
    const int ib1 = min(max(rb - 3, 0), ROWS - 7);
    const int d10 = ib1 - ib0;                 // 0 or 1, warp-uniform
    const int base_s = ib0 - r0 + 3;

    const float zc0 = shz[(2 * ty + 3) * TP + (tx + 3)].x;
    const float zc1 = shz[(2 * ty + 4) * TP + (tx + 3)].x;

    // Per-pixel center terms.
    const float xc0 = zc0 * cfc, yc0 = zc0 * (((float)ra - CYc) * invFY);
    const float xc1 = zc1 * cfc, yc1 = zc1 * (((float)rb - CYc) * invFY);
    float pc20 = xc0 * xc0; pc20 = fmaf(yc0, yc0, pc20); pc20 = fmaf(zc0, zc0, pc20);
    float pc21 = xc1 * xc1; pc21 = fmaf(yc1, yc1, pc21); pc21 = fmaf(zc1, zc1, pc21);
    const float m2x0 = -2.0f * xc0, m2y0 = -2.0f * yc0, m2z0 = -2.0f * zc0;
    const float m2x1 = -2.0f * xc1, m2y1 = -2.0f * yc1, m2z1 = -2.0f * zc1;
    const u64 m2x01 = pack2(m2x0, m2x1);
    const u64 pc201 = pack2(pc20, pc21);

    float s1_0 = 0.0f, s1_1 = 0.0f;
    u64 s2p = pack2(0.0f, 0.0f);
    float s2e0 = 0.0f, s2e1 = 0.0f;    // edge-row side sums

    const u64* __restrict__ rp0 =
        reinterpret_cast<const u64*>(&shz[base_s * TP + jb_s]);
    const float rf0 = ((float)ib0 - CYc) * invFY;

    if (d10 == 0) {
        // Windows coincide: all 7 rows packed.
        #pragma unroll
        for (int t = 0; t < 7; t++)
            row2(rp0 + t * TP, cfd, rf0 + (float)t * invFY,
                 m2y0, m2z0, m2y1, m2z1, m2x01, pc201, s1_0, s1_1, s2p);
    } else {
        // Offset windows: row 0 p0-only, rows 1..6 packed, row 7 p1-only.
        row1(rp0, cfd, rf0, m2y0, m2z0, m2x0, pc20, s1_0, s2e0);
        #pragma unroll
        for (int t = 1; t <= 6; t++)
            row2(rp0 + t * TP, cfd, rf0 + (float)t * invFY,
                 m2y0, m2z0, m2y1, m2z1, m2x01, pc201, s1_0, s1_1, s2p);
        row1(rp0 + 7 * TP, cfd, rf0 + 7.0f * invFY,
             m2y1, m2z1, m2x1, pc21, s1_1, s2e1);
    }

    float s2_0, s2_1;
    unpack2(s2p, s2_0, s2_1);
    s2_0 += s2e0;
    s2_1 += s2e1;

    // var = (sum d^2 - (sum d)^2/49) / 48  (Bessel-corrected), per pixel.
    float total;
    {
        const float mean0 = s1_0 * (1.0f / 49.0f);
        float var0 = fmaf(-mean0, s1_0, s2_0) * (1.0f / 48.0f);
        var0 = fmaxf(var0, 0.0f);
        const float mean1 = s1_1 * (1.0f / 49.0f);
        float var1 = fmaf(-mean1, s1_1, s2_1) * (1.0f / 48.0f);
        var1 = fmaxf(var1, 0.0f);
        total  = (zc0 > 0.0f) ? sqrt_abs(var0) : 0.0f;
        total += (zc1 > 0.0f) ? sqrt_abs(var1) : 0.0f;
    }

    // Deterministic warp shuffle reduction, then cross-warp via smem.
    #pragma unroll
    for (int k = 16; k > 0; k >>= 1)
        total += __shfl_down_sync(0xFFFFFFFFu, total, k);
    if ((tid & 31) == 0) red[tid >> 5] = total;
    __syncthreads();

    // Fused final reduction: last arriving block sums all partials in
    // fixed index order (deterministic), writes out, re-arms counter.
    if (tid == 0) {
        g_partials[blockIdx.y * GRIDX + blockIdx.x] =
            (red[0] + red[1]) + (red[2] + red[3]);
        __threadfence();
        const unsigned int t = atomicAdd(&g_count, 1u);
        s_last = (t == NPART - 1) ? 1u : 0u;
    }
    __syncthreads();

    if (s_last) {
        const volatile float* vp = g_partials;
        float s = 0.0f;
        for (int i = tid; i < NPART; i += NT) s += vp[i];
        #pragma unroll
        for (int k = 16; k > 0; k >>= 1)
            s += __shfl_down_sync(0xFFFFFFFFu, s, k);
        if ((tid & 31) == 0) red[tid >> 5] = s;
        __syncthreads();
        if (tid == 0) {
            out[0] = ((red[0] + red[1]) + (red[2] + red[3])) * 100.0f;
            g_count = 0;   // re-arm for next graph replay
        }
    }
}

extern "C" void kernel_launch(void* const* d_in, const int* in_sizes, int n_in,
                              void* d_out, int out_size) {
    const float* depth = (const float*)d_in[0];
    float* out = (float*)d_out;

    dim3 grid(GRIDX, GRIDY);
    dim3 block(BX, BY);
    stdev_kernel<<<grid, block>>>(depth, out);
}